// round 13
// baseline (speedup 1.0000x reference)
#include <cuda_runtime.h>
#include <cuda_bf16.h>

// out[i,j,:] = float(argmax(encoding_logits[clamp(qv[i,j],-128,127)+128, :]))
// (soft_codes - stop_gradient(soft_codes) == 0 exactly; gumbel_noise unused)
//
// R13: exact R4 geometry (proven best: 32 pixels/block, 8 threads/pixel,
// 8 x STG.128 per thread, 8192 blocks) with the ONE untried store policy:
// write-through (st.global.wt) instead of evict-first (.cs). WT avoids
// creating dirty L2 lines for write-once data, removing writeback-scheduler
// pressure from the DRAM write path. LTS accept cap (~6300 B/cyc) bounds
// both; this probes whether writeback churn was a co-limiter below it.

#define N_LEVELS 256
#define N_PIX (512 * 512)

__device__ float g_hard_table[N_LEVELS];

// Stage 1: one WARP per row (256 warps = 32 blocks x 8 warps). Lane l scans
// columns l, l+32, ..., l+224 (coalesced), then shuffle-reduce with
// first-index tiebreak (matching jnp.argmax).
__global__ void argmax_rows_kernel(const float* __restrict__ logits) {
    int warp = (blockIdx.x * blockDim.x + threadIdx.x) >> 5;   // row 0..255
    int lane = threadIdx.x & 31;
    const float* row = logits + warp * N_LEVELS;

    float best = -__FLT_MAX__;
    int bi = N_LEVELS;
#pragma unroll
    for (int j = 0; j < N_LEVELS / 32; ++j) {
        int k = lane + j * 32;
        float v = row[k];
        if (v > best || (v == best && k < bi)) { best = v; bi = k; }
    }
#pragma unroll
    for (int off = 16; off > 0; off >>= 1) {
        float ov = __shfl_down_sync(0xffffffffu, best, off);
        int oi = __shfl_down_sync(0xffffffffu, bi, off);
        if (ov > best || (ov == best && oi < bi)) { best = ov; bi = oi; }
    }
    if (lane == 0) g_hard_table[warp] = (float)bi;
}

// Stage 2: resolve pixel value once per thread, then stream 8 independent
// write-through STG.128. Block covers 32 pixels (128 KB contiguous):
//   8 threads per pixel; thread t -> pixel (t>>3), f4 offsets (t&7)+8j.
// Per-warp store instruction = 4 full 128-byte lines (fully coalesced).
__global__ void __launch_bounds__(256) broadcast_kernel(
    const int* __restrict__ qv, float4* __restrict__ out) {
    int t = threadIdx.x;
    int pix = blockIdx.x * 32 + (t >> 3);         // pixel index
    int q = __ldg(qv + pix);
    q = min(max(q, -128), 127) + 128;
    float v = g_hard_table[q];
    float4 v4 = make_float4(v, v, v, v);

    float4* p = out + (long long)pix * 64 + (t & 7);
#pragma unroll
    for (int j = 0; j < 8; ++j)
        __stwt(p + j * 8, v4);                    // write-through
}

extern "C" void kernel_launch(void* const* d_in, const int* in_sizes, int n_in,
                              void* d_out, int out_size) {
    const int* qv = (const int*)d_in[0];           // [512,512] int32
    const float* logits = (const float*)d_in[1];   // [256,256] f32
    // d_in[2] (gumbel_noise) is mathematically unused.
    float4* out = (float4*)d_out;

    argmax_rows_kernel<<<32, 256>>>(logits);       // 256 warps, 1 per row

    broadcast_kernel<<<N_PIX / 32, 256>>>(qv, out); // 8192 blocks
}

// round 14
// speedup vs baseline: 1.0911x; 1.0911x over previous
#include <cuda_runtime.h>
#include <cuda_bf16.h>

// out[i,j,:] = float(argmax(encoding_logits[clamp(qv[i,j],-128,127)+128, :]))
// (soft_codes - stop_gradient(soft_codes) == 0 exactly; gumbel_noise unused)
//
// TERMINAL (R4 config, best measured 41.44 us):
// 268.4 MB of mandatory stores pinned at the B300 LTS write-accept cap
// (~6300 B/cyc = 6.5 TB/s L2 ingress). Invariant across 9 structural
// variants: store width 128/256b; eviction .cs/default/split/.wt;
// 4/8/16 stores per thread; grids 4096/8192/16384; spin-fusion; PDL;
// L2-residency. TMA store path documented same-cap. Argmax stage and
// launch boundary hide under graph-replay pipelining. Identical-source
// resubmits span 41.4-42.9 us (wall-clock noise +-0.7 us).

#define N_LEVELS 256
#define N_PIX (512 * 512)

__device__ float g_hard_table[N_LEVELS];

// Stage 1: one WARP per row (256 warps = 32 blocks x 8 warps). Lane l scans
// columns l, l+32, ..., l+224 (coalesced), then shuffle-reduce with
// first-index tiebreak (matching jnp.argmax).
__global__ void argmax_rows_kernel(const float* __restrict__ logits) {
    int warp = (blockIdx.x * blockDim.x + threadIdx.x) >> 5;   // row 0..255
    int lane = threadIdx.x & 31;
    const float* row = logits + warp * N_LEVELS;

    float best = -__FLT_MAX__;
    int bi = N_LEVELS;
#pragma unroll
    for (int j = 0; j < N_LEVELS / 32; ++j) {
        int k = lane + j * 32;
        float v = row[k];
        if (v > best || (v == best && k < bi)) { best = v; bi = k; }
    }
#pragma unroll
    for (int off = 16; off > 0; off >>= 1) {
        float ov = __shfl_down_sync(0xffffffffu, best, off);
        int oi = __shfl_down_sync(0xffffffffu, bi, off);
        if (ov > best || (ov == best && oi < bi)) { best = ov; bi = oi; }
    }
    if (lane == 0) g_hard_table[warp] = (float)bi;
}

// Stage 2: resolve pixel value once per thread, then stream 8 independent
// evict-first STG.128. Block covers 32 pixels (128 KB contiguous):
//   8 threads per pixel; thread t -> pixel (t>>3), f4 offsets (t&7)+8j.
// Per-warp store instruction = 4 full 128-byte lines (fully coalesced).
__global__ void __launch_bounds__(256) broadcast_kernel(
    const int* __restrict__ qv, float4* __restrict__ out) {
    int t = threadIdx.x;
    int pix = blockIdx.x * 32 + (t >> 3);         // pixel index
    int q = __ldg(qv + pix);
    q = min(max(q, -128), 127) + 128;
    float v = g_hard_table[q];
    float4 v4 = make_float4(v, v, v, v);

    float4* p = out + (long long)pix * 64 + (t & 7);
#pragma unroll
    for (int j = 0; j < 8; ++j)
        __stcs(p + j * 8, v4);
}

extern "C" void kernel_launch(void* const* d_in, const int* in_sizes, int n_in,
                              void* d_out, int out_size) {
    const int* qv = (const int*)d_in[0];           // [512,512] int32
    const float* logits = (const float*)d_in[1];   // [256,256] f32
    // d_in[2] (gumbel_noise) is mathematically unused.
    float4* out = (float4*)d_out;

    argmax_rows_kernel<<<32, 256>>>(logits);       // 256 warps, 1 per row

    broadcast_kernel<<<N_PIX / 32, 256>>>(qv, out); // 8192 blocks
}